// round 2
// baseline (speedup 1.0000x reference)
#include <cuda_runtime.h>

#define NMAX 50000
#define EMAX 800000
#define GROW 512   // 32 h * 16 o

// Scratch (static device globals -- no runtime allocation)
__device__ __align__(16) float g_buf[(size_t)NMAX * GROW];   // ~102.4 MB
__device__ float xb_buf[NMAX * 16];
__device__ float sum_buf[NMAX * 16];
__device__ float cnt_buf[NMAX];
__device__ int   src_idx[EMAX];
__device__ int   dst_idx[EMAX];
__device__ int   idx_is64;

// ---------------------------------------------------------------------------
// Kernel 0a: detect edge_index dtype. If the buffer is int64 (little-endian,
// values < 2^31), every odd 32-bit word of the first 64 is the zero high-half.
// ---------------------------------------------------------------------------
__global__ void detect_idx_kernel(const int* __restrict__ raw) {
    if (threadIdx.x == 0 && blockIdx.x == 0) {
        int all_zero = 1;
        for (int k = 1; k < 64; k += 2)
            if (raw[k] != 0) { all_zero = 0; break; }
        idx_is64 = all_zero;
    }
}

// ---------------------------------------------------------------------------
// Kernel 0b: decode edge_index into int32 src/dst arrays.
// ---------------------------------------------------------------------------
__global__ void decode_idx_kernel(const void* __restrict__ raw, int E) {
    int i = blockIdx.x * blockDim.x + threadIdx.x;
    if (i >= 2 * E) return;
    int v;
    if (idx_is64) v = (int)((const long long*)raw)[i];
    else          v = ((const int*)raw)[i];
    if (i < E) src_idx[i] = v;
    else       dst_idx[i - E] = v;
}

// ---------------------------------------------------------------------------
// Kernel A: per-node precompute
//   g[n][h][o] = sum_i x[n][i] * w2[h*256 + i*16 + o]
//   xb[n][o]   = sum_i x[n][i] * b2[i*16 + o]
//   also zeroes sum_buf / cnt_buf for this node.
// One block (128 threads) per node; each thread produces a float4 of g.
// ---------------------------------------------------------------------------
__global__ void node_pre_kernel(const float* __restrict__ x,
                                const float* __restrict__ w2,
                                const float* __restrict__ b2) {
    int n = blockIdx.x;
    int t = threadIdx.x;          // 0..127
    __shared__ float xs[16];
    if (t < 16) xs[t] = x[n * 16 + t];
    __syncthreads();

    int c0 = t * 4;               // output index within the 512-row
    int h  = c0 >> 4;             // 0..31
    int o0 = c0 & 15;             // 0,4,8,12

    float4 acc = make_float4(0.f, 0.f, 0.f, 0.f);
#pragma unroll
    for (int i = 0; i < 16; i++) {
        float4 w = *reinterpret_cast<const float4*>(w2 + h * 256 + i * 16 + o0);
        float xi = xs[i];
        acc.x = fmaf(xi, w.x, acc.x);
        acc.y = fmaf(xi, w.y, acc.y);
        acc.z = fmaf(xi, w.z, acc.z);
        acc.w = fmaf(xi, w.w, acc.w);
    }
    *reinterpret_cast<float4*>(g_buf + (size_t)n * GROW + c0) = acc;

    if (t < 16) {
        float a = 0.f;
#pragma unroll
        for (int i = 0; i < 16; i++) a = fmaf(xs[i], b2[i * 16 + t], a);
        xb_buf[n * 16 + t] = a;
        sum_buf[n * 16 + t] = 0.f;
    }
    if (t == 0) cnt_buf[n] = 0.f;
}

// ---------------------------------------------------------------------------
// Kernel B: one warp per edge.
//   h[32] = relu(ea @ w1 + b1)       (lane l owns h[l])
//   msg[o] = xb[src][o] + sum_h h[h] * g[src][h*16+o]
//   atomic scatter into sum_buf[dst], cnt_buf[dst].
// g row is read fully coalesced: iteration k, lane l reads g[k*32 + l].
// ---------------------------------------------------------------------------
__global__ void edge_kernel(const float* __restrict__ ea,
                            const float* __restrict__ w1,
                            const float* __restrict__ b1,
                            int E) {
    __shared__ float w1s[16 * 32];
    __shared__ float b1s[32];
    int tid = threadIdx.x;
    for (int j = tid; j < 16 * 32; j += blockDim.x) w1s[j] = w1[j];
    if (tid < 32) b1s[tid] = b1[tid];
    __syncthreads();

    int warp = tid >> 5;
    int lane = tid & 31;
    int e = blockIdx.x * (blockDim.x >> 5) + warp;
    if (e >= E) return;

    // layer 1: each lane computes one hidden unit
    float eav = (lane < 16) ? ea[(size_t)e * 16 + lane] : 0.f;
    float acc = b1s[lane];
#pragma unroll
    for (int i = 0; i < 16; i++) {
        float xi = __shfl_sync(0xffffffffu, eav, i);
        acc = fmaf(xi, w1s[i * 32 + lane], acc);
    }
    float h = fmaxf(acc, 0.f);

    int src = src_idx[e];
    int dst = dst_idx[e];

    // contraction over the precomputed g row (coalesced 128B per iteration)
    const float* g = g_buf + (size_t)src * GROW;
    int base_h = lane >> 4;       // 0 or 1
    float partial = 0.f;
#pragma unroll
    for (int k = 0; k < 16; k++) {
        float gv = g[k * 32 + lane];                             // idx = k*32+lane
        float hv = __shfl_sync(0xffffffffu, h, 2 * k + base_h);  // h[idx>>4]
        partial = fmaf(hv, gv, partial);
    }
    // lanes l and l^16 hold the two h-parities for the same o = l&15
    partial += __shfl_xor_sync(0xffffffffu, partial, 16);

    if (lane < 16) {
        float msg = partial + xb_buf[src * 16 + lane];
        atomicAdd(&sum_buf[dst * 16 + lane], msg);
    }
    if (lane == 0) atomicAdd(&cnt_buf[dst], 1.0f);
}

// ---------------------------------------------------------------------------
// Kernel C: out[n][o] = sum[n][o]/max(cnt,1) + x[n]@root[:,o] + bias[o]
// ---------------------------------------------------------------------------
__global__ void finalize_kernel(const float* __restrict__ x,
                                const float* __restrict__ root,
                                const float* __restrict__ bias,
                                float* __restrict__ out, int N) {
    int idx = blockIdx.x * blockDim.x + threadIdx.x;
    if (idx >= N * 16) return;
    int n = idx >> 4;
    int o = idx & 15;
    float c = cnt_buf[n];
    float a = sum_buf[idx] / fmaxf(c, 1.0f);
    float r = 0.f;
#pragma unroll
    for (int i = 0; i < 16; i++) r = fmaf(x[n * 16 + i], root[i * 16 + o], r);
    out[idx] = a + r + bias[o];
}

extern "C" void kernel_launch(void* const* d_in, const int* in_sizes, int n_in,
                              void* d_out, int out_size) {
    const float* x    = (const float*)d_in[0];
    const void*  ei   = d_in[1];
    const float* ea   = (const float*)d_in[2];
    const float* w1   = (const float*)d_in[3];
    const float* b1   = (const float*)d_in[4];
    const float* w2   = (const float*)d_in[5];
    const float* b2   = (const float*)d_in[6];
    const float* root = (const float*)d_in[7];
    const float* bias = (const float*)d_in[8];
    float*       out  = (float*)d_out;

    int N = in_sizes[0] / 16;
    int E = in_sizes[2] / 16;

    detect_idx_kernel<<<1, 32>>>((const int*)ei);
    decode_idx_kernel<<<(2 * E + 255) / 256, 256>>>(ei, E);

    node_pre_kernel<<<N, 128>>>(x, w2, b2);

    int edges_per_block = 256 / 32;  // 8 warps
    int nblk = (E + edges_per_block - 1) / edges_per_block;
    edge_kernel<<<nblk, 256>>>(ea, w1, b1, E);

    finalize_kernel<<<(N * 16 + 255) / 256, 256>>>(x, root, bias, out, N);
}